// round 14
// baseline (speedup 1.0000x reference)
#include <cuda_runtime.h>
#include <cuda_fp16.h>
#include <cstdint>

#define DM 0.9394130628134758f
#define DS 0.7788007830714049f
#define TH 0.3f
#define INVSC (1.0f/4096.0f)

#define N_L0 (16*64*64*64)
#define N_L1 (16*64*64*128)
#define N_L2 (16*32*32*128)
#define N_P2 (16*32768)
#define N_L3 (16*512)
#define N_L4 (16*11)
#define N_PART (16*16*512)
#define SZ_S0B (16*4356*64)
#define SZ_P1B (16*1156*128)
#define NW1PK4 (9*2*4*8*32)
#define NW2PK4 (9*2*8*8*32)

__device__ float g_vm0[N_L0], g_vs0[N_L0];
__device__ float g_vm1[N_L1], g_vs1[N_L1];
__device__ float g_vm2[N_L2], g_vs2[N_L2];
__device__ float g_vm3[N_L3], g_vs3[N_L3];
__device__ float g_vm4[N_L4], g_vs4[N_L4];
__device__ float g_part[N_PART];
__device__ float g_out[N_L4];
__device__ __half g_s0b[2 * SZ_S0B];     /* double-buffered (pipeline) */
__device__ __half g_p1b[SZ_P1B];
__device__ __half g_p2b[2 * N_P2];       /* double-buffered (pipeline) */
__device__ uint4 g_w1pk[NW1PK4];
__device__ uint4 g_w2pk[NW2PK4];

__device__ __forceinline__ float srm_ns(float I, float* vm, float* vs, size_t idx) {
    float v = vm[idx], w = vs[idx];
    float k = ((v - w) > TH) ? 0.f : 1.f;
    float a = DM * v * k + I;
    float c = DS * w * k + I;
    float sn = ((a - c) > TH) ? 1.0f : 0.0f;
    vm[idx] = a; vs[idx] = c;
    return sn;
}

__device__ __forceinline__ void srm2_ns(float I0, float I1, float* vm, float* vs,
                                        size_t idx, float& s0, float& s1) {
    float2 vmv = *(float2*)(vm + idx);
    float2 vsv = *(float2*)(vs + idx);
    float k0 = ((vmv.x - vsv.x) > TH) ? 0.f : 1.f;
    float k1 = ((vmv.y - vsv.y) > TH) ? 0.f : 1.f;
    float a0 = DM * vmv.x * k0 + I0, a1 = DM * vmv.y * k1 + I1;
    float b0 = DS * vsv.x * k0 + I0, b1 = DS * vsv.y * k1 + I1;
    s0 = ((a0 - b0) > TH) ? 1.f : 0.f;
    s1 = ((a1 - b1) > TH) ? 1.f : 0.f;
    *(float2*)(vm + idx) = make_float2(a0, a1);
    *(float2*)(vs + idx) = make_float2(b0, b1);
}

__global__ void zero_all() {
    int stride = gridDim.x * blockDim.x;
    int i0 = blockIdx.x * blockDim.x + threadIdx.x;
    for (int i = i0; i < N_L0; i += stride) { g_vm0[i] = 0.f; g_vs0[i] = 0.f; }
    for (int i = i0; i < N_L1; i += stride) { g_vm1[i] = 0.f; g_vs1[i] = 0.f; }
    for (int i = i0; i < N_L2; i += stride) { g_vm2[i] = 0.f; g_vs2[i] = 0.f; }
    for (int i = i0; i < N_L3; i += stride) { g_vm3[i] = 0.f; g_vs3[i] = 0.f; }
    for (int i = i0; i < N_L4; i += stride) { g_vm4[i] = 0.f; g_vs4[i] = 0.f; g_out[i] = 0.f; }
    unsigned* a = (unsigned*)g_s0b;
    for (int i = i0; i < SZ_S0B; i += stride) a[i] = 0u;   /* both buffers */
    unsigned* c = (unsigned*)g_p1b;
    for (int i = i0; i < SZ_P1B / 2; i += stride) c[i] = 0u;
}

__device__ __forceinline__ unsigned pick_split_pack_h(float wa, float wb, int split) {
    __half ha = __float2half_rn(wa);
    __half hb = __float2half_rn(wb);
    __half va, vb;
    if (split == 0) { va = ha; vb = hb; }
    else {
        va = __float2half_rn((wa - __half2float(ha)) * 4096.0f);
        vb = __float2half_rn((wb - __half2float(hb)) * 4096.0f);
    }
    return (unsigned)__half_as_ushort(va) | ((unsigned)__half_as_ushort(vb) << 16);
}

__global__ void pack_w(const float* __restrict__ W, uint4* __restrict__ Bpk, int CIN, int total) {
    int idx = blockIdx.x * 256 + threadIdx.x;
    if (idx >= total) return;
    int KC = CIN / 16;
    int lane = idx & 31;
    int p = (idx >> 5) & 7;
    int rest = idx >> 8;
    int kc = rest % KC; rest /= KC;
    int split = rest & 1; int tap = rest >> 1;
    int ky = tap / 3, kx = tap % 3;
    int k0 = kc * 16 + (lane & 3) * 2;
    int n0 = (2 * p) * 8 + (lane >> 2);
    int n1 = n0 + 8;
    uint4 v;
    {
        float w0 = W[((size_t)(n0 * CIN + k0 + 0) * 3 + ky) * 3 + kx];
        float w1 = W[((size_t)(n0 * CIN + k0 + 1) * 3 + ky) * 3 + kx];
        float w8 = W[((size_t)(n0 * CIN + k0 + 8) * 3 + ky) * 3 + kx];
        float w9 = W[((size_t)(n0 * CIN + k0 + 9) * 3 + ky) * 3 + kx];
        v.x = pick_split_pack_h(w0, w1, split);
        v.y = pick_split_pack_h(w8, w9, split);
    }
    {
        float w0 = W[((size_t)(n1 * CIN + k0 + 0) * 3 + ky) * 3 + kx];
        float w1 = W[((size_t)(n1 * CIN + k0 + 1) * 3 + ky) * 3 + kx];
        float w8 = W[((size_t)(n1 * CIN + k0 + 8) * 3 + ky) * 3 + kx];
        float w9 = W[((size_t)(n1 * CIN + k0 + 9) * 3 + ky) * 3 + kx];
        v.z = pick_split_pack_h(w0, w1, split);
        v.w = pick_split_pack_h(w8, w9, split);
    }
    Bpk[idx] = v;
}

__global__ void __launch_bounds__(256)
conv0_srm(const float* __restrict__ x, const float* __restrict__ W0, int t,
          __half* __restrict__ s0out) {
    __shared__ float ins[2 * 360];
    __shared__ float ws[16 * 2 * 12];
    __shared__ float sacc[256 * 17];
    int tid = threadIdx.x;
    int b = blockIdx.z, cog = blockIdx.y;
    int tX = blockIdx.x & 3, tY = blockIdx.x >> 2;
    int x0 = tX * 16, y0 = tY * 16;
    const float* xb = x + ((size_t)(b * 16 + t)) * 2 * 4096;
    for (int i = tid; i < 2 * 324; i += 256) {
        int ci = i / 324; int r = i - ci * 324;
        int y = r / 18;   int xq = r - y * 18;
        int gy = y0 + y - 1, gx = x0 + xq - 1;
        float v = 0.f;
        if ((unsigned)gy < 64u && (unsigned)gx < 64u) {
            v = __ldg(xb + ci * 4096 + gy * 64 + gx);
            v = fminf(fmaxf(v, 0.f), 1.f);
        }
        ins[ci * 360 + y * 20 + xq] = v;
    }
    for (int i = tid; i < 16 * 18; i += 256) {
        int col = i / 18; int r = i - col * 18;
        int ci = r / 9;   int k = r - ci * 9;
        ws[(col * 2 + ci) * 12 + k] = __ldg(W0 + ((size_t)(cog * 16 + col) * 2 + ci) * 9 + k);
    }
    __syncthreads();
    int ty = tid >> 4, tx = tid & 15;
    float acc[16];
#pragma unroll
    for (int j = 0; j < 16; j++) acc[j] = 0.f;
#pragma unroll
    for (int ci = 0; ci < 2; ci++) {
        const float* ip = ins + ci * 360 + ty * 20 + tx;
        float iv[3][3];
#pragma unroll
        for (int yy = 0; yy < 3; yy++)
#pragma unroll
            for (int xx = 0; xx < 3; xx++) iv[yy][xx] = ip[yy * 20 + xx];
#pragma unroll
        for (int j = 0; j < 16; j++) {
            const float* wb = ws + (j * 2 + ci) * 12;
            float4 wA = *(const float4*)wb;
            float4 wB = *(const float4*)(wb + 4);
            float w8 = wb[8];
            float s = acc[j];
            s += iv[0][0] * wA.x; s += iv[0][1] * wA.y; s += iv[0][2] * wA.z;
            s += iv[1][0] * wA.w; s += iv[1][1] * wB.x; s += iv[1][2] * wB.y;
            s += iv[2][0] * wB.z; s += iv[2][1] * wB.w; s += iv[2][2] * w8;
            acc[j] = s;
        }
    }
#pragma unroll
    for (int c = 0; c < 16; c++) sacc[(ty * 16 + tx) * 17 + c] = acc[c];
    __syncthreads();
#pragma unroll
    for (int q = 0; q < 4; q++) {
        int f = q * 256 + tid;
        int yl = f >> 6, fi = f & 63;
        int xl = fi >> 2, cq = fi & 3;
        size_t rowb = (((size_t)(cog * 16 + b) * 4096) + (y0 + yl) * 64 + x0) * 16;
        float4 vmv = *(float4*)(g_vm0 + rowb + fi * 4);
        float4 vsv = *(float4*)(g_vs0 + rowb + fi * 4);
        const float* sp = sacc + (yl * 16 + xl) * 17 + cq * 4;
        float I0 = sp[0], I1 = sp[1], I2 = sp[2], I3 = sp[3];
        float k0 = ((vmv.x - vsv.x) > TH) ? 0.f : 1.f;
        float k1 = ((vmv.y - vsv.y) > TH) ? 0.f : 1.f;
        float k2 = ((vmv.z - vsv.z) > TH) ? 0.f : 1.f;
        float k3 = ((vmv.w - vsv.w) > TH) ? 0.f : 1.f;
        float a0 = DM * vmv.x * k0 + I0, a1 = DM * vmv.y * k1 + I1;
        float a2 = DM * vmv.z * k2 + I2, a3 = DM * vmv.w * k3 + I3;
        float c0 = DS * vsv.x * k0 + I0, c1 = DS * vsv.y * k1 + I1;
        float c2 = DS * vsv.z * k2 + I2, c3 = DS * vsv.w * k3 + I3;
        float s0 = ((a0 - c0) > TH) ? 1.f : 0.f;
        float s1 = ((a1 - c1) > TH) ? 1.f : 0.f;
        float s2 = ((a2 - c2) > TH) ? 1.f : 0.f;
        float s3 = ((a3 - c3) > TH) ? 1.f : 0.f;
        *(float4*)(g_vm0 + rowb + fi * 4) = make_float4(a0, a1, a2, a3);
        *(float4*)(g_vs0 + rowb + fi * 4) = make_float4(c0, c1, c2, c3);
        int gy = y0 + yl, gx = x0 + xl;
        size_t qi = ((size_t)b * 4356 + (gy + 1) * 66 + (gx + 1)) * 64 + cog * 16 + cq * 4;
        *(__half2*)(s0out + qi)     = __floats2half2_rn(s0, s1);
        *(__half2*)(s0out + qi + 2) = __floats2half2_rn(s2, s3);
    }
}

__device__ __forceinline__ void mma16816h(float* c, const unsigned* a, unsigned b0, unsigned b1) {
    asm volatile(
        "mma.sync.aligned.m16n8k16.row.col.f32.f16.f16.f32 "
        "{%0,%1,%2,%3}, {%4,%5,%6,%7}, {%8,%9}, {%0,%1,%2,%3};\n"
        : "+f"(c[0]), "+f"(c[1]), "+f"(c[2]), "+f"(c[3])
        : "r"(a[0]), "r"(a[1]), "r"(a[2]), "r"(a[3]), "r"(b0), "r"(b1));
}

__device__ __forceinline__ void ldsm4(unsigned& r0, unsigned& r1, unsigned& r2, unsigned& r3,
                                      uint32_t addr) {
    asm volatile("ldmatrix.sync.aligned.m8n8.x4.shared.b16 {%0,%1,%2,%3}, [%4];\n"
                 : "=r"(r0), "=r"(r1), "=r"(r2), "=r"(r3) : "r"(addr));
}

// Implicit-GEMM conv, JT=1 (8 co per warp, 32 per CTA) -> ~75 regs -> 3 CTAs/SM.
// Per-accumulator accumulation order identical to previous rounds (bit-exact).
template<int HW, int CIN, int YROWS, int SHIFT, bool IS_CONV2>
__global__ void __launch_bounds__(256, 3)
conv_mma(const __half* __restrict__ Abuf, const uint4* __restrict__ Bpk,
         float* __restrict__ vm, float* __restrict__ vs,
         __half* __restrict__ poolb, __half* __restrict__ p2out)
{
    const int WB = HW + 2, QTOT = WB * WB, KC = CIN / 16;
    const int PITCHE = CIN + 8;
    const int SLABROWS = (YROWS + 2) * WB;
    const int CPR = CIN / 8;
    extern __shared__ __align__(16) unsigned char dsm[];
    __half* As = (__half*)dsm;

    int tid = threadIdx.x, lane = tid & 31, wid = tid >> 5;
    int warp_m = wid >> 2, warp_n = wid & 3;
    int b = blockIdx.z;
    int cogBase = blockIdx.y * 32;
    int y0 = blockIdx.x * YROWS;
    int q0 = y0 * WB;

    for (int i = tid; i < SLABROWS * CPR; i += 256) {
        int rrow = i / CPR, cw = i - rrow * CPR;
        uint4 v = __ldg((const uint4*)(Abuf + ((size_t)b * QTOT + q0 + rrow) * CIN) + cw);
        *(uint4*)(As + rrow * PITCHE + cw * 8) = v;
    }
    __syncthreads();

    int mtg[4];
#pragma unroll
    for (int l = 0; l < 4; l++)
        mtg[l] = (YROWS == 2) ? (warp_m * 2 + (l & 1) + ((l & 2) << 1)) : (warp_m * 4 + l);

    uint32_t sm32 = (uint32_t)__cvta_generic_to_shared(As);
    uint32_t abase[4];
#pragma unroll
    for (int l = 0; l < 4; l++) {
        int m = mtg[l] * 16 + (lane & 15);
        int pr = (m >> SHIFT) * WB + (m & (HW - 1));
        abase[l] = sm32 + (uint32_t)(pr * PITCHE * 2) + ((lane >> 4) & 1) * 16;
    }

    float acc[2][4][4];   // [split][mtile][frag]
#pragma unroll
    for (int s = 0; s < 2; s++)
#pragma unroll
        for (int l = 0; l < 4; l++)
#pragma unroll
            for (int c = 0; c < 4; c++) acc[s][l][c] = 0.f;

    // B as uint2 stream: single n-tile (8 co) per warp.
    int nt = cogBase / 8 + warp_n;                 // n-tile index
    const uint2* bt2 = (const uint2*)Bpk;
    // uint2 index = (((tap*2+s)*KC + kc)*8 + (nt>>1))*64 + lane*2 + (nt&1)
    const uint2* btl = bt2 + (size_t)(nt >> 1) * 64 + lane * 2 + (nt & 1);

#pragma unroll 1
    for (int tap = 0; tap < 9; tap++) {
        int ky = tap / 3, kx = tap - ky * 3;
        uint32_t ta[4];
#pragma unroll
        for (int l = 0; l < 4; l++) ta[l] = abase[l] + (uint32_t)((ky * WB + kx) * PITCHE * 2);
        const uint2* bt = btl + (size_t)(tap * 2) * (KC * 512);
#pragma unroll
        for (int kc = 0; kc < KC; kc++) {
            unsigned a[4][4];
#pragma unroll
            for (int l = 0; l < 4; l++)
                ldsm4(a[l][0], a[l][1], a[l][2], a[l][3], ta[l] + kc * 32);
#pragma unroll
            for (int s = 0; s < 2; s++) {
                uint2 bb = __ldg(bt + (size_t)(s * KC + kc) * 512);
#pragma unroll
                for (int l = 0; l < 4; l++)
                    mma16816h(acc[s][l], a[l], bb.x, bb.y);
            }
        }
    }

#pragma unroll
    for (int lp = 0; lp < 2; lp++) {
#pragma unroll
        for (int o = 0; o < 2; o++) {
            int mA = mtg[lp] * 16 + (lane >> 2) + o * 8;
            int mB = mtg[lp + 2] * 16 + (lane >> 2) + o * 8;
            int yA = y0 + (mA >> SHIFT), xA = mA & (HW - 1);
            int yB = y0 + (mB >> SHIFT);
            int co = cogBase + warp_n * 8 + (lane & 3) * 2;
            size_t iA = ((size_t)(b * HW * HW) + yA * HW + xA) * 128 + co;
            size_t iB = ((size_t)(b * HW * HW) + yB * HW + xA) * 128 + co;
            float IA0 = acc[0][lp][o * 2 + 0]     + acc[1][lp][o * 2 + 0]     * INVSC;
            float IA1 = acc[0][lp][o * 2 + 1]     + acc[1][lp][o * 2 + 1]     * INVSC;
            float IB0 = acc[0][lp + 2][o * 2 + 0] + acc[1][lp + 2][o * 2 + 0] * INVSC;
            float IB1 = acc[0][lp + 2][o * 2 + 1] + acc[1][lp + 2][o * 2 + 1] * INVSC;
            float sA0, sA1, sB0, sB1;
            srm2_ns(IA0, IA1, vm, vs, iA, sA0, sA1);
            srm2_ns(IB0, IB1, vm, vs, iB, sB0, sB1);
            float xA0 = fmaxf(sA0, __shfl_xor_sync(0xffffffffu, sA0, 4));
            float xA1 = fmaxf(sA1, __shfl_xor_sync(0xffffffffu, sA1, 4));
            float xB0 = fmaxf(sB0, __shfl_xor_sync(0xffffffffu, sB0, 4));
            float xB1 = fmaxf(sB1, __shfl_xor_sync(0xffffffffu, sB1, 4));
            float p0 = fmaxf(xA0, xB0);
            float p1 = fmaxf(xA1, xB1);
            if ((lane & 4) == 0) {
                int yp = yA >> 1, xp = xA >> 1;
                if (IS_CONV2) {
                    p2out[(size_t)b * 32768 + co * 256 + yp * 16 + xp] = __float2half(p0);
                    p2out[(size_t)b * 32768 + (co + 1) * 256 + yp * 16 + xp] = __float2half(p1);
                } else {
                    size_t qi = ((size_t)b * 1156 + (yp + 1) * 34 + (xp + 1)) * 128 + co;
                    *reinterpret_cast<__half2*>(poolb + qi) = __floats2half2_rn(p0, p1);
                }
            }
        }
    }
}

__global__ void __launch_bounds__(256)
fc3_partial(const float* __restrict__ W3, const __half* __restrict__ p2) {
    extern __shared__ __half p2s[];
    int ks = blockIdx.x, jg = blockIdx.y;
    int k0 = ks * 2048;
    int tid = threadIdx.x;
    for (int i = tid; i < 4096; i += 256) {
        int b = i >> 8, c = i & 255;
        ((uint4*)p2s)[i] = __ldg((const uint4*)(p2 + (size_t)b * 32768 + k0) + c);
    }
    __syncthreads();
    int wj = tid >> 5, lane = tid & 31;
    const uint2* ps = (const uint2*)p2s;
#pragma unroll 1
    for (int jj = 0; jj < 4; jj++) {
        int j = jg * 32 + wj * 4 + jj;
        const float4* wr = (const float4*)(W3 + (size_t)j * 32768 + k0);
        float acc[16];
#pragma unroll
        for (int b = 0; b < 16; b++) acc[b] = 0.f;
#pragma unroll 1
        for (int kk = lane; kk < 512; kk += 32) {
            float4 w4 = __ldg(wr + kk);
#pragma unroll
            for (int b = 0; b < 16; b++) {
                uint2 pv = ps[b * 512 + kk];
                float2 lo = __half22float2(*(const __half2*)&pv.x);
                float2 hi = __half22float2(*(const __half2*)&pv.y);
                acc[b] += w4.x * lo.x; acc[b] += w4.y * lo.y;
                acc[b] += w4.z * hi.x; acc[b] += w4.w * hi.y;
            }
        }
#pragma unroll
        for (int b = 0; b < 16; b++) {
            float v = acc[b];
            v += __shfl_down_sync(0xffffffffu, v, 16);
            v += __shfl_down_sync(0xffffffffu, v, 8);
            v += __shfl_down_sync(0xffffffffu, v, 4);
            v += __shfl_down_sync(0xffffffffu, v, 2);
            v += __shfl_down_sync(0xffffffffu, v, 1);
            if (lane == 0) g_part[(ks * 16 + b) * 512 + j] = v;
        }
    }
}

__global__ void __launch_bounds__(1024) fc34_srm(const float* __restrict__ W4) {
    __shared__ float s3s[8192];
    int tid = threadIdx.x;
#pragma unroll
    for (int e = 0; e < 8; e++) {
        int i = e * 1024 + tid;
        float I = 0.f;
#pragma unroll
        for (int ks = 0; ks < 16; ks++) I += g_part[ks * 8192 + i];
        s3s[i] = srm_ns(I, g_vm3, g_vs3, i);
    }
    __syncthreads();
    if (tid < 176) {
        int b = tid / 11, j = tid % 11;
        const float4* wr = (const float4*)(W4 + j * 512);
        const float4* sr = (const float4*)(s3s + b * 512);
        float acc = 0.f;
#pragma unroll 4
        for (int k = 0; k < 128; k++) {
            float4 w = __ldg(wr + k), s = sr[k];
            acc += w.x * s.x; acc += w.y * s.y; acc += w.z * s.z; acc += w.w * s.w;
        }
        float sn = srm_ns(acc, g_vm4, g_vs4, tid);
        g_out[tid] += sn;
    }
}

__global__ void finalize_k(float* __restrict__ out) {
    int i = threadIdx.x;
    if (i < 176) out[i] = g_out[i] * 0.0625f;
}

// ---------------------------------------------------------------------------
// Pipeline resources (round-11/13 schedule): created once at static init.
struct PipeCtx {
    cudaStream_t sA, sC;
    cudaEvent_t evInit, evJoinA, evJoinC;
    cudaEvent_t evA[16], evB1[16], evB2[16], evC3[16];
    PipeCtx() {
        cudaStreamCreateWithFlags(&sA, cudaStreamNonBlocking);
        cudaStreamCreateWithFlags(&sC, cudaStreamNonBlocking);
        cudaEventCreateWithFlags(&evInit, cudaEventDisableTiming);
        cudaEventCreateWithFlags(&evJoinA, cudaEventDisableTiming);
        cudaEventCreateWithFlags(&evJoinC, cudaEventDisableTiming);
        for (int i = 0; i < 16; i++) {
            cudaEventCreateWithFlags(&evA[i], cudaEventDisableTiming);
            cudaEventCreateWithFlags(&evB1[i], cudaEventDisableTiming);
            cudaEventCreateWithFlags(&evB2[i], cudaEventDisableTiming);
            cudaEventCreateWithFlags(&evC3[i], cudaEventDisableTiming);
        }
    }
};
static PipeCtx g_pipe;

extern "C" void kernel_launch(void* const* d_in, const int* in_sizes, int n_in,
                              void* d_out, int out_size) {
    (void)in_sizes; (void)n_in; (void)out_size;
    const float* x  = (const float*)d_in[0];
    const float* W0 = (const float*)d_in[1];
    const float* W1 = (const float*)d_in[2];
    const float* W2 = (const float*)d_in[3];
    const float* W3 = (const float*)d_in[4];
    const float* W4 = (const float*)d_in[5];
    float* out = (float*)d_out;

    const int SMEM1 = 264 * 144;
    const int SMEM2 = 204 * 272;
    cudaFuncSetAttribute((const void*)conv_mma<64, 64, 2, 6, false>,
                         cudaFuncAttributeMaxDynamicSharedMemorySize, SMEM1);
    cudaFuncSetAttribute((const void*)conv_mma<32, 128, 4, 5, true>,
                         cudaFuncAttributeMaxDynamicSharedMemorySize, SMEM2);
    cudaFuncSetAttribute((const void*)fc3_partial,
                         cudaFuncAttributeMaxDynamicSharedMemorySize, 65536);

    __half *s0b, *p1b, *p2b;
    uint4 *w1pk, *w2pk;
    float *vm1, *vs1, *vm2, *vs2;
    cudaGetSymbolAddress((void**)&s0b, g_s0b);
    cudaGetSymbolAddress((void**)&p1b, g_p1b);
    cudaGetSymbolAddress((void**)&p2b, g_p2b);
    cudaGetSymbolAddress((void**)&w1pk, g_w1pk);
    cudaGetSymbolAddress((void**)&w2pk, g_w2pk);
    cudaGetSymbolAddress((void**)&vm1, g_vm1);
    cudaGetSymbolAddress((void**)&vs1, g_vs1);
    cudaGetSymbolAddress((void**)&vm2, g_vm2);
    cudaGetSymbolAddress((void**)&vs2, g_vs2);

    zero_all<<<2048, 256>>>();
    pack_w<<<(NW1PK4 + 255) / 256, 256>>>(W1, w1pk, 64, NW1PK4);
    pack_w<<<(NW2PK4 + 255) / 256, 256>>>(W2, w2pk, 128, NW2PK4);
    cudaEventRecord(g_pipe.evInit, 0);
    cudaStreamWaitEvent(g_pipe.sA, g_pipe.evInit, 0);

    for (int t = 0; t < 16; t++) {
        __half* s0t = s0b + (size_t)(t & 1) * SZ_S0B;
        __half* p2t = p2b + (size_t)(t & 1) * N_P2;

        // Stream A: conv0(t). Waits conv1(t-2) (s0b buffer reuse).
        if (t >= 2) cudaStreamWaitEvent(g_pipe.sA, g_pipe.evB1[t - 2], 0);
        conv0_srm<<<dim3(16, 4, 16), 256, 0, g_pipe.sA>>>(x, W0, t, s0t);
        cudaEventRecord(g_pipe.evA[t], g_pipe.sA);

        // Default stream B: conv1(t) (waits conv0(t)), conv2(t).
        cudaStreamWaitEvent(0, g_pipe.evA[t], 0);
        conv_mma<64, 64, 2, 6, false><<<dim3(32, 4, 16), 256, SMEM1>>>(
            s0t, w1pk, vm1, vs1, p1b, nullptr);
        cudaEventRecord(g_pipe.evB1[t], 0);
        if (t >= 2) cudaStreamWaitEvent(0, g_pipe.evC3[t - 2], 0);   // p2b reuse
        conv_mma<32, 128, 4, 5, true><<<dim3(8, 4, 16), 256, SMEM2>>>(
            p1b, w2pk, vm2, vs2, nullptr, p2t);
        cudaEventRecord(g_pipe.evB2[t], 0);

        // Stream C: fc3(t) (waits conv2(t)), fc34(t).
        cudaStreamWaitEvent(g_pipe.sC, g_pipe.evB2[t], 0);
        fc3_partial<<<dim3(16, 16), 256, 65536, g_pipe.sC>>>(W3, p2t);
        cudaEventRecord(g_pipe.evC3[t], g_pipe.sC);
        fc34_srm<<<1, 1024, 0, g_pipe.sC>>>(W4);
    }

    cudaEventRecord(g_pipe.evJoinA, g_pipe.sA);
    cudaEventRecord(g_pipe.evJoinC, g_pipe.sC);
    cudaStreamWaitEvent(0, g_pipe.evJoinA, 0);
    cudaStreamWaitEvent(0, g_pipe.evJoinC, 0);
    finalize_k<<<1, 256>>>(out);
}

// round 16
// speedup vs baseline: 1.2027x; 1.2027x over previous
#include <cuda_runtime.h>
#include <cuda_fp16.h>
#include <cstdint>

#define DM 0.9394130628134758f
#define DS 0.7788007830714049f
#define TH 0.3f
#define INVSC (1.0f/4096.0f)

#define N_L0 (16*64*64*64)
#define N_L1 (16*64*64*128)
#define N_L2 (16*32*32*128)
#define N_P2 (16*32768)
#define N_L3 (16*512)
#define N_L4 (16*11)
#define N_PART (16*16*512)
#define SZ_S0B (16*4356*64)
#define SZ_P1B (16*1156*128)
#define NW1PK4 (9*2*4*8*32)
#define NW2PK4 (9*2*8*8*32)

__device__ float g_vm0[N_L0], g_vs0[N_L0];
__device__ float g_vm1[N_L1], g_vs1[N_L1];
__device__ float g_vm2[N_L2], g_vs2[N_L2];
__device__ float g_vm3[N_L3], g_vs3[N_L3];
__device__ float g_vm4[N_L4], g_vs4[N_L4];
__device__ float g_part[N_PART];
__device__ float g_out[N_L4];
__device__ __half g_s0b[2 * SZ_S0B];     /* double-buffered (pipeline) */
__device__ __half g_p1b[SZ_P1B];
__device__ __half g_p2b[2 * N_P2];       /* double-buffered (pipeline) */
__device__ uint4 g_w1pk[NW1PK4];
__device__ uint4 g_w2pk[NW2PK4];

__device__ __forceinline__ float srm_ns(float I, float* vm, float* vs, size_t idx) {
    float v = vm[idx], w = vs[idx];
    float k = ((v - w) > TH) ? 0.f : 1.f;
    float a = DM * v * k + I;
    float c = DS * w * k + I;
    float sn = ((a - c) > TH) ? 1.0f : 0.0f;
    vm[idx] = a; vs[idx] = c;
    return sn;
}

__device__ __forceinline__ void srm2_ns(float I0, float I1, float* vm, float* vs,
                                        size_t idx, float& s0, float& s1) {
    float2 vmv = *(float2*)(vm + idx);
    float2 vsv = *(float2*)(vs + idx);
    float k0 = ((vmv.x - vsv.x) > TH) ? 0.f : 1.f;
    float k1 = ((vmv.y - vsv.y) > TH) ? 0.f : 1.f;
    float a0 = DM * vmv.x * k0 + I0, a1 = DM * vmv.y * k1 + I1;
    float b0 = DS * vsv.x * k0 + I0, b1 = DS * vsv.y * k1 + I1;
    s0 = ((a0 - b0) > TH) ? 1.f : 0.f;
    s1 = ((a1 - b1) > TH) ? 1.f : 0.f;
    *(float2*)(vm + idx) = make_float2(a0, a1);
    *(float2*)(vs + idx) = make_float2(b0, b1);
}

__global__ void zero_all() {
    int stride = gridDim.x * blockDim.x;
    int i0 = blockIdx.x * blockDim.x + threadIdx.x;
    for (int i = i0; i < N_L0; i += stride) { g_vm0[i] = 0.f; g_vs0[i] = 0.f; }
    for (int i = i0; i < N_L1; i += stride) { g_vm1[i] = 0.f; g_vs1[i] = 0.f; }
    for (int i = i0; i < N_L2; i += stride) { g_vm2[i] = 0.f; g_vs2[i] = 0.f; }
    for (int i = i0; i < N_L3; i += stride) { g_vm3[i] = 0.f; g_vs3[i] = 0.f; }
    for (int i = i0; i < N_L4; i += stride) { g_vm4[i] = 0.f; g_vs4[i] = 0.f; g_out[i] = 0.f; }
    unsigned* a = (unsigned*)g_s0b;
    for (int i = i0; i < SZ_S0B; i += stride) a[i] = 0u;   /* both buffers */
    unsigned* c = (unsigned*)g_p1b;
    for (int i = i0; i < SZ_P1B / 2; i += stride) c[i] = 0u;
}

__device__ __forceinline__ unsigned pick_split_pack_h(float wa, float wb, int split) {
    __half ha = __float2half_rn(wa);
    __half hb = __float2half_rn(wb);
    __half va, vb;
    if (split == 0) { va = ha; vb = hb; }
    else {
        va = __float2half_rn((wa - __half2float(ha)) * 4096.0f);
        vb = __float2half_rn((wb - __half2float(hb)) * 4096.0f);
    }
    return (unsigned)__half_as_ushort(va) | ((unsigned)__half_as_ushort(vb) << 16);
}

__global__ void pack_w(const float* __restrict__ W, uint4* __restrict__ Bpk, int CIN, int total) {
    int idx = blockIdx.x * 256 + threadIdx.x;
    if (idx >= total) return;
    int KC = CIN / 16;
    int lane = idx & 31;
    int p = (idx >> 5) & 7;
    int rest = idx >> 8;
    int kc = rest % KC; rest /= KC;
    int split = rest & 1; int tap = rest >> 1;
    int ky = tap / 3, kx = tap % 3;
    int k0 = kc * 16 + (lane & 3) * 2;
    int n0 = (2 * p) * 8 + (lane >> 2);
    int n1 = n0 + 8;
    uint4 v;
    {
        float w0 = W[((size_t)(n0 * CIN + k0 + 0) * 3 + ky) * 3 + kx];
        float w1 = W[((size_t)(n0 * CIN + k0 + 1) * 3 + ky) * 3 + kx];
        float w8 = W[((size_t)(n0 * CIN + k0 + 8) * 3 + ky) * 3 + kx];
        float w9 = W[((size_t)(n0 * CIN + k0 + 9) * 3 + ky) * 3 + kx];
        v.x = pick_split_pack_h(w0, w1, split);
        v.y = pick_split_pack_h(w8, w9, split);
    }
    {
        float w0 = W[((size_t)(n1 * CIN + k0 + 0) * 3 + ky) * 3 + kx];
        float w1 = W[((size_t)(n1 * CIN + k0 + 1) * 3 + ky) * 3 + kx];
        float w8 = W[((size_t)(n1 * CIN + k0 + 8) * 3 + ky) * 3 + kx];
        float w9 = W[((size_t)(n1 * CIN + k0 + 9) * 3 + ky) * 3 + kx];
        v.z = pick_split_pack_h(w0, w1, split);
        v.w = pick_split_pack_h(w8, w9, split);
    }
    Bpk[idx] = v;
}

__global__ void __launch_bounds__(256)
conv0_srm(const float* __restrict__ x, const float* __restrict__ W0, int t,
          __half* __restrict__ s0out) {
    __shared__ float ins[2 * 360];
    __shared__ float ws[16 * 2 * 12];
    __shared__ float sacc[256 * 17];
    int tid = threadIdx.x;
    int b = blockIdx.z, cog = blockIdx.y;
    int tX = blockIdx.x & 3, tY = blockIdx.x >> 2;
    int x0 = tX * 16, y0 = tY * 16;
    const float* xb = x + ((size_t)(b * 16 + t)) * 2 * 4096;
    for (int i = tid; i < 2 * 324; i += 256) {
        int ci = i / 324; int r = i - ci * 324;
        int y = r / 18;   int xq = r - y * 18;
        int gy = y0 + y - 1, gx = x0 + xq - 1;
        float v = 0.f;
        if ((unsigned)gy < 64u && (unsigned)gx < 64u) {
            v = __ldg(xb + ci * 4096 + gy * 64 + gx);
            v = fminf(fmaxf(v, 0.f), 1.f);
        }
        ins[ci * 360 + y * 20 + xq] = v;
    }
    for (int i = tid; i < 16 * 18; i += 256) {
        int col = i / 18; int r = i - col * 18;
        int ci = r / 9;   int k = r - ci * 9;
        ws[(col * 2 + ci) * 12 + k] = __ldg(W0 + ((size_t)(cog * 16 + col) * 2 + ci) * 9 + k);
    }
    __syncthreads();
    int ty = tid >> 4, tx = tid & 15;
    float acc[16];
#pragma unroll
    for (int j = 0; j < 16; j++) acc[j] = 0.f;
#pragma unroll
    for (int ci = 0; ci < 2; ci++) {
        const float* ip = ins + ci * 360 + ty * 20 + tx;
        float iv[3][3];
#pragma unroll
        for (int yy = 0; yy < 3; yy++)
#pragma unroll
            for (int xx = 0; xx < 3; xx++) iv[yy][xx] = ip[yy * 20 + xx];
#pragma unroll
        for (int j = 0; j < 16; j++) {
            const float* wb = ws + (j * 2 + ci) * 12;
            float4 wA = *(const float4*)wb;
            float4 wB = *(const float4*)(wb + 4);
            float w8 = wb[8];
            float s = acc[j];
            s += iv[0][0] * wA.x; s += iv[0][1] * wA.y; s += iv[0][2] * wA.z;
            s += iv[1][0] * wA.w; s += iv[1][1] * wB.x; s += iv[1][2] * wB.y;
            s += iv[2][0] * wB.z; s += iv[2][1] * wB.w; s += iv[2][2] * w8;
            acc[j] = s;
        }
    }
#pragma unroll
    for (int c = 0; c < 16; c++) sacc[(ty * 16 + tx) * 17 + c] = acc[c];
    __syncthreads();
#pragma unroll
    for (int q = 0; q < 4; q++) {
        int f = q * 256 + tid;
        int yl = f >> 6, fi = f & 63;
        int xl = fi >> 2, cq = fi & 3;
        size_t rowb = (((size_t)(cog * 16 + b) * 4096) + (y0 + yl) * 64 + x0) * 16;
        float4 vmv = *(float4*)(g_vm0 + rowb + fi * 4);
        float4 vsv = *(float4*)(g_vs0 + rowb + fi * 4);
        const float* sp = sacc + (yl * 16 + xl) * 17 + cq * 4;
        float I0 = sp[0], I1 = sp[1], I2 = sp[2], I3 = sp[3];
        float k0 = ((vmv.x - vsv.x) > TH) ? 0.f : 1.f;
        float k1 = ((vmv.y - vsv.y) > TH) ? 0.f : 1.f;
        float k2 = ((vmv.z - vsv.z) > TH) ? 0.f : 1.f;
        float k3 = ((vmv.w - vsv.w) > TH) ? 0.f : 1.f;
        float a0 = DM * vmv.x * k0 + I0, a1 = DM * vmv.y * k1 + I1;
        float a2 = DM * vmv.z * k2 + I2, a3 = DM * vmv.w * k3 + I3;
        float c0 = DS * vsv.x * k0 + I0, c1 = DS * vsv.y * k1 + I1;
        float c2 = DS * vsv.z * k2 + I2, c3 = DS * vsv.w * k3 + I3;
        float s0 = ((a0 - c0) > TH) ? 1.f : 0.f;
        float s1 = ((a1 - c1) > TH) ? 1.f : 0.f;
        float s2 = ((a2 - c2) > TH) ? 1.f : 0.f;
        float s3 = ((a3 - c3) > TH) ? 1.f : 0.f;
        *(float4*)(g_vm0 + rowb + fi * 4) = make_float4(a0, a1, a2, a3);
        *(float4*)(g_vs0 + rowb + fi * 4) = make_float4(c0, c1, c2, c3);
        int gy = y0 + yl, gx = x0 + xl;
        size_t qi = ((size_t)b * 4356 + (gy + 1) * 66 + (gx + 1)) * 64 + cog * 16 + cq * 4;
        *(__half2*)(s0out + qi)     = __floats2half2_rn(s0, s1);
        *(__half2*)(s0out + qi + 2) = __floats2half2_rn(s2, s3);
    }
}

__device__ __forceinline__ void mma16816h(float* c, const unsigned* a, unsigned b0, unsigned b1) {
    asm volatile(
        "mma.sync.aligned.m16n8k16.row.col.f32.f16.f16.f32 "
        "{%0,%1,%2,%3}, {%4,%5,%6,%7}, {%8,%9}, {%0,%1,%2,%3};\n"
        : "+f"(c[0]), "+f"(c[1]), "+f"(c[2]), "+f"(c[3])
        : "r"(a[0]), "r"(a[1]), "r"(a[2]), "r"(a[3]), "r"(b0), "r"(b1));
}

__device__ __forceinline__ void ldsm4(unsigned& r0, unsigned& r1, unsigned& r2, unsigned& r3,
                                      uint32_t addr) {
    asm volatile("ldmatrix.sync.aligned.m8n8.x4.shared.b16 {%0,%1,%2,%3}, [%4];\n"
                 : "=r"(r0), "=r"(r1), "=r"(r2), "=r"(r3) : "r"(addr));
}

// Implicit-GEMM conv (round-13 proven config): JT=2, software-pipelined mainloop.
template<int HW, int CIN, int YROWS, int SHIFT, bool IS_CONV2>
__global__ void __launch_bounds__(256, 2)
conv_mma(const __half* __restrict__ Abuf, const uint4* __restrict__ Bpk,
         float* __restrict__ vm, float* __restrict__ vs,
         __half* __restrict__ poolb, __half* __restrict__ p2out)
{
    const int WB = HW + 2, QTOT = WB * WB, KC = CIN / 16;
    const int PITCHE = CIN + 8;
    const int SLABROWS = (YROWS + 2) * WB;
    const int CPR = CIN / 8;
    const int JT = 2;
    extern __shared__ __align__(16) unsigned char dsm[];
    __half* As = (__half*)dsm;

    int tid = threadIdx.x, lane = tid & 31, wid = tid >> 5;
    int warp_m = wid >> 2, warp_n = wid & 3;
    int b = blockIdx.z;
    int cogBase = blockIdx.y * 32 * JT;
    int y0 = blockIdx.x * YROWS;
    int q0 = y0 * WB;

    for (int i = tid; i < SLABROWS * CPR; i += 256) {
        int rrow = i / CPR, cw = i - rrow * CPR;
        uint4 v = __ldg((const uint4*)(Abuf + ((size_t)b * QTOT + q0 + rrow) * CIN) + cw);
        *(uint4*)(As + rrow * PITCHE + cw * 8) = v;
    }
    __syncthreads();

    int mtg[4];
#pragma unroll
    for (int l = 0; l < 4; l++)
        mtg[l] = (YROWS == 2) ? (warp_m * 2 + (l & 1) + ((l & 2) << 1)) : (warp_m * 4 + l);

    uint32_t sm32 = (uint32_t)__cvta_generic_to_shared(As);
    uint32_t abase[4];
#pragma unroll
    for (int l = 0; l < 4; l++) {
        int m = mtg[l] * 16 + (lane & 15);
        int pr = (m >> SHIFT) * WB + (m & (HW - 1));
        abase[l] = sm32 + (uint32_t)(pr * PITCHE * 2) + ((lane >> 4) & 1) * 16;
    }

    float acc[2][4][JT][4];
#pragma unroll
    for (int s = 0; s < 2; s++)
#pragma unroll
        for (int l = 0; l < 4; l++)
#pragma unroll
            for (int j = 0; j < JT; j++)
#pragma unroll
                for (int c = 0; c < 4; c++) acc[s][l][j][c] = 0.f;

    int ntp = cogBase / 16 + warp_n;
    const uint4* btl = Bpk + (size_t)ntp * 32 + lane;

#pragma unroll 1
    for (int tap = 0; tap < 9; tap++) {
        int ky = tap / 3, kx = tap - ky * 3;
        uint32_t ta[4];
#pragma unroll
        for (int l = 0; l < 4; l++) ta[l] = abase[l] + (uint32_t)((ky * WB + kx) * PITCHE * 2);
        const uint4* bt = btl + (size_t)tap * (2 * KC * 256);

        unsigned a[2][4][4];
#pragma unroll
        for (int l = 0; l < 4; l++)
            ldsm4(a[0][l][0], a[0][l][1], a[0][l][2], a[0][l][3], ta[l]);
        uint4 bb = __ldg(bt);

#pragma unroll
        for (int kc = 0; kc < KC; kc++) {
            int cur = kc & 1, nxt = cur ^ 1;
            if (kc + 1 < KC) {
#pragma unroll
                for (int l = 0; l < 4; l++)
                    ldsm4(a[nxt][l][0], a[nxt][l][1], a[nxt][l][2], a[nxt][l][3],
                          ta[l] + (kc + 1) * 32);
            }
#pragma unroll
            for (int s = 0; s < 2; s++) {
                uint4 bbn = bb;
                if (s == 0)               bbn = __ldg(bt + (KC + kc) * 256);
                else if (kc + 1 < KC)     bbn = __ldg(bt + (kc + 1) * 256);
#pragma unroll
                for (int l = 0; l < 4; l++) {
                    mma16816h(acc[s][l][0], a[cur][l], bb.x, bb.y);
                    mma16816h(acc[s][l][1], a[cur][l], bb.z, bb.w);
                }
                bb = bbn;
            }
        }
    }

#pragma unroll
    for (int lp = 0; lp < 2; lp++) {
#pragma unroll
        for (int o = 0; o < 2; o++) {
            int mA = mtg[lp] * 16 + (lane >> 2) + o * 8;
            int mB = mtg[lp + 2] * 16 + (lane >> 2) + o * 8;
            int yA = y0 + (mA >> SHIFT), xA = mA & (HW - 1);
            int yB = y0 + (mB >> SHIFT);
#pragma unroll
            for (int j = 0; j < JT; j++) {
                int co = cogBase + warp_n * 8 * JT + j * 8 + (lane & 3) * 2;
                size_t iA = ((size_t)(b * HW * HW) + yA * HW + xA) * 128 + co;
                size_t iB = ((size_t)(b * HW * HW) + yB * HW + xA) * 128 + co;
                float IA0 = acc[0][lp][j][o * 2 + 0]     + acc[1][lp][j][o * 2 + 0]     * INVSC;
                float IA1 = acc[0][lp][j][o * 2 + 1]     + acc[1][lp][j][o * 2 + 1]     * INVSC;
                float IB0 = acc[0][lp + 2][j][o * 2 + 0] + acc[1][lp + 2][j][o * 2 + 0] * INVSC;
                float IB1 = acc[0][lp + 2][j][o * 2 + 1] + acc[1][lp + 2][j][o * 2 + 1] * INVSC;
                float sA0, sA1, sB0, sB1;
                srm2_ns(IA0, IA1, vm, vs, iA, sA0, sA1);
                srm2_ns(IB0, IB1, vm, vs, iB, sB0, sB1);
                float xA0 = fmaxf(sA0, __shfl_xor_sync(0xffffffffu, sA0, 4));
                float xA1 = fmaxf(sA1, __shfl_xor_sync(0xffffffffu, sA1, 4));
                float xB0 = fmaxf(sB0, __shfl_xor_sync(0xffffffffu, sB0, 4));
                float xB1 = fmaxf(sB1, __shfl_xor_sync(0xffffffffu, sB1, 4));
                float p0 = fmaxf(xA0, xB0);
                float p1 = fmaxf(xA1, xB1);
                if ((lane & 4) == 0) {
                    int yp = yA >> 1, xp = xA >> 1;
                    if (IS_CONV2) {
                        p2out[(size_t)b * 32768 + co * 256 + yp * 16 + xp] = __float2half(p0);
                        p2out[(size_t)b * 32768 + (co + 1) * 256 + yp * 16 + xp] = __float2half(p1);
                    } else {
                        size_t qi = ((size_t)b * 1156 + (yp + 1) * 34 + (xp + 1)) * 128 + co;
                        *reinterpret_cast<__half2*>(poolb + qi) = __floats2half2_rn(p0, p1);
                    }
                }
            }
        }
    }
}

__global__ void __launch_bounds__(256)
fc3_partial(const float* __restrict__ W3, const __half* __restrict__ p2) {
    extern __shared__ __half p2s[];
    int ks = blockIdx.x, jg = blockIdx.y;
    int k0 = ks * 2048;
    int tid = threadIdx.x;
    for (int i = tid; i < 4096; i += 256) {
        int b = i >> 8, c = i & 255;
        ((uint4*)p2s)[i] = __ldg((const uint4*)(p2 + (size_t)b * 32768 + k0) + c);
    }
    __syncthreads();
    int wj = tid >> 5, lane = tid & 31;
    const uint2* ps = (const uint2*)p2s;
#pragma unroll 1
    for (int jj = 0; jj < 4; jj++) {
        int j = jg * 32 + wj * 4 + jj;
        const float4* wr = (const float4*)(W3 + (size_t)j * 32768 + k0);
        float acc[16];
#pragma unroll
        for (int b = 0; b < 16; b++) acc[b] = 0.f;
#pragma unroll 1
        for (int kk = lane; kk < 512; kk += 32) {
            float4 w4 = __ldg(wr + kk);
#pragma unroll
            for (int b = 0; b < 16; b++) {
                uint2 pv = ps[b * 512 + kk];
                float2 lo = __half22float2(*(const __half2*)&pv.x);
                float2 hi = __half22float2(*(const __half2*)&pv.y);
                acc[b] += w4.x * lo.x; acc[b] += w4.y * lo.y;
                acc[b] += w4.z * hi.x; acc[b] += w4.w * hi.y;
            }
        }
#pragma unroll
        for (int b = 0; b < 16; b++) {
            float v = acc[b];
            v += __shfl_down_sync(0xffffffffu, v, 16);
            v += __shfl_down_sync(0xffffffffu, v, 8);
            v += __shfl_down_sync(0xffffffffu, v, 4);
            v += __shfl_down_sync(0xffffffffu, v, 2);
            v += __shfl_down_sync(0xffffffffu, v, 1);
            if (lane == 0) g_part[(ks * 16 + b) * 512 + j] = v;
        }
    }
}

__global__ void __launch_bounds__(1024) fc34_srm(const float* __restrict__ W4) {
    __shared__ float s3s[8192];
    int tid = threadIdx.x;
#pragma unroll
    for (int e = 0; e < 8; e++) {
        int i = e * 1024 + tid;
        float I = 0.f;
#pragma unroll
        for (int ks = 0; ks < 16; ks++) I += g_part[ks * 8192 + i];
        s3s[i] = srm_ns(I, g_vm3, g_vs3, i);
    }
    __syncthreads();
    if (tid < 176) {
        int b = tid / 11, j = tid % 11;
        const float4* wr = (const float4*)(W4 + j * 512);
        const float4* sr = (const float4*)(s3s + b * 512);
        float acc = 0.f;
#pragma unroll 4
        for (int k = 0; k < 128; k++) {
            float4 w = __ldg(wr + k), s = sr[k];
            acc += w.x * s.x; acc += w.y * s.y; acc += w.z * s.z; acc += w.w * s.w;
        }
        float sn = srm_ns(acc, g_vm4, g_vs4, tid);
        g_out[tid] += sn;
    }
}

__global__ void finalize_k(float* __restrict__ out) {
    int i = threadIdx.x;
    if (i < 176) out[i] = g_out[i] * 0.0625f;
}

// ---------------------------------------------------------------------------
// Pipeline resources (round-13 schedule): created once at static init.
struct PipeCtx {
    cudaStream_t sA, sC;
    cudaEvent_t evInit, evJoinA, evJoinC;
    cudaEvent_t evA[16], evB1[16], evB2[16], evC3[16];
    PipeCtx() {
        cudaStreamCreateWithFlags(&sA, cudaStreamNonBlocking);
        cudaStreamCreateWithFlags(&sC, cudaStreamNonBlocking);
        cudaEventCreateWithFlags(&evInit, cudaEventDisableTiming);
        cudaEventCreateWithFlags(&evJoinA, cudaEventDisableTiming);
        cudaEventCreateWithFlags(&evJoinC, cudaEventDisableTiming);
        for (int i = 0; i < 16; i++) {
            cudaEventCreateWithFlags(&evA[i], cudaEventDisableTiming);
            cudaEventCreateWithFlags(&evB1[i], cudaEventDisableTiming);
            cudaEventCreateWithFlags(&evB2[i], cudaEventDisableTiming);
            cudaEventCreateWithFlags(&evC3[i], cudaEventDisableTiming);
        }
    }
};
static PipeCtx g_pipe;

extern "C" void kernel_launch(void* const* d_in, const int* in_sizes, int n_in,
                              void* d_out, int out_size) {
    (void)in_sizes; (void)n_in; (void)out_size;
    const float* x  = (const float*)d_in[0];
    const float* W0 = (const float*)d_in[1];
    const float* W1 = (const float*)d_in[2];
    const float* W2 = (const float*)d_in[3];
    const float* W3 = (const float*)d_in[4];
    const float* W4 = (const float*)d_in[5];
    float* out = (float*)d_out;

    const int SMEM1 = 264 * 144;
    const int SMEM2 = 204 * 272;
    cudaFuncSetAttribute((const void*)conv_mma<64, 64, 2, 6, false>,
                         cudaFuncAttributeMaxDynamicSharedMemorySize, SMEM1);
    cudaFuncSetAttribute((const void*)conv_mma<32, 128, 4, 5, true>,
                         cudaFuncAttributeMaxDynamicSharedMemorySize, SMEM2);
    cudaFuncSetAttribute((const void*)fc3_partial,
                         cudaFuncAttributeMaxDynamicSharedMemorySize, 65536);

    __half *s0b, *p1b, *p2b;
    uint4 *w1pk, *w2pk;
    float *vm1, *vs1, *vm2, *vs2;
    cudaGetSymbolAddress((void**)&s0b, g_s0b);
    cudaGetSymbolAddress((void**)&p1b, g_p1b);
    cudaGetSymbolAddress((void**)&p2b, g_p2b);
    cudaGetSymbolAddress((void**)&w1pk, g_w1pk);
    cudaGetSymbolAddress((void**)&w2pk, g_w2pk);
    cudaGetSymbolAddress((void**)&vm1, g_vm1);
    cudaGetSymbolAddress((void**)&vs1, g_vs1);
    cudaGetSymbolAddress((void**)&vm2, g_vm2);
    cudaGetSymbolAddress((void**)&vs2, g_vs2);

    zero_all<<<2048, 256>>>();
    pack_w<<<(NW1PK4 + 255) / 256, 256>>>(W1, w1pk, 64, NW1PK4);
    pack_w<<<(NW2PK4 + 255) / 256, 256>>>(W2, w2pk, 128, NW2PK4);
    cudaEventRecord(g_pipe.evInit, 0);
    cudaStreamWaitEvent(g_pipe.sA, g_pipe.evInit, 0);

    for (int t = 0; t < 16; t++) {
        __half* s0t = s0b + (size_t)(t & 1) * SZ_S0B;
        __half* p2t = p2b + (size_t)(t & 1) * N_P2;

        // Stream A: conv0(t). Waits conv1(t-2) (s0b buffer reuse).
        if (t >= 2) cudaStreamWaitEvent(g_pipe.sA, g_pipe.evB1[t - 2], 0);
        conv0_srm<<<dim3(16, 4, 16), 256, 0, g_pipe.sA>>>(x, W0, t, s0t);
        cudaEventRecord(g_pipe.evA[t], g_pipe.sA);

        // Default stream B: conv1(t) (waits conv0(t)), conv2(t).
        cudaStreamWaitEvent(0, g_pipe.evA[t], 0);
        conv_mma<64, 64, 2, 6, false><<<dim3(32, 2, 16), 256, SMEM1>>>(
            s0t, w1pk, vm1, vs1, p1b, nullptr);
        cudaEventRecord(g_pipe.evB1[t], 0);
        if (t >= 2) cudaStreamWaitEvent(0, g_pipe.evC3[t - 2], 0);   // p2b reuse
        conv_mma<32, 128, 4, 5, true><<<dim3(8, 2, 16), 256, SMEM2>>>(
            p1b, w2pk, vm2, vs2, nullptr, p2t);
        cudaEventRecord(g_pipe.evB2[t], 0);

        // Stream C: fc3(t) (waits conv2(t)), fc34(t).
        cudaStreamWaitEvent(g_pipe.sC, g_pipe.evB2[t], 0);
        fc3_partial<<<dim3(16, 16), 256, 65536, g_pipe.sC>>>(W3, p2t);
        cudaEventRecord(g_pipe.evC3[t], g_pipe.sC);
        fc34_srm<<<1, 1024, 0, g_pipe.sC>>>(W4);
    }

    cudaEventRecord(g_pipe.evJoinA, g_pipe.sA);
    cudaEventRecord(g_pipe.evJoinC, g_pipe.sC);
    cudaStreamWaitEvent(0, g_pipe.evJoinA, 0);
    cudaStreamWaitEvent(0, g_pipe.evJoinC, 0);
    finalize_k<<<1, 256>>>(out);
}

// round 17
// speedup vs baseline: 1.2385x; 1.0298x over previous
#include <cuda_runtime.h>
#include <cuda_fp16.h>
#include <cstdint>

#define DM 0.9394130628134758f
#define DS 0.7788007830714049f
#define TH 0.3f
#define INVSC (1.0f/4096.0f)

#define N_L0 (16*64*64*64)
#define N_L1 (16*64*64*128)
#define N_L2 (16*32*32*128)
#define N_P2 (16*32768)
#define N_L3 (16*512)
#define N_L4 (16*11)
#define N_PART (16*16*512)
#define SZ_S0B (16*4356*64)
#define SZ_P1B (16*1156*128)
#define NW1PK4 (9*2*4*8*32)
#define NW2PK4 (9*2*8*8*32)

__device__ float g_vm0[N_L0], g_vs0[N_L0];
__device__ float g_vm1[N_L1], g_vs1[N_L1];
__device__ float g_vm2[N_L2], g_vs2[N_L2];
__device__ float g_vm3[N_L3], g_vs3[N_L3];
__device__ float g_vm4[N_L4], g_vs4[N_L4];
__device__ float g_part[N_PART];
__device__ float g_out[N_L4];
__device__ __half g_s0b[2 * SZ_S0B];     /* double-buffered (pipeline) */
__device__ __half g_p1b[SZ_P1B];
__device__ __half g_p2b[2 * N_P2];       /* double-buffered (pipeline) */
__device__ uint4 g_w1pk[NW1PK4];
__device__ uint4 g_w2pk[NW2PK4];

__device__ __forceinline__ float srm_ns(float I, float* vm, float* vs, size_t idx) {
    float v = vm[idx], w = vs[idx];
    float k = ((v - w) > TH) ? 0.f : 1.f;
    float a = DM * v * k + I;
    float c = DS * w * k + I;
    float sn = ((a - c) > TH) ? 1.0f : 0.0f;
    vm[idx] = a; vs[idx] = c;
    return sn;
}

// First-step aware: when first!=0, state is known-zero -> a=c=I, s=0 (bit-exact).
__device__ __forceinline__ void srm2_nsf(float I0, float I1, float* vm, float* vs,
                                         size_t idx, int first, float& s0, float& s1) {
    float2 vmv, vsv;
    if (first) { vmv = make_float2(0.f, 0.f); vsv = make_float2(0.f, 0.f); }
    else       { vmv = *(float2*)(vm + idx);  vsv = *(float2*)(vs + idx); }
    float k0 = ((vmv.x - vsv.x) > TH) ? 0.f : 1.f;
    float k1 = ((vmv.y - vsv.y) > TH) ? 0.f : 1.f;
    float a0 = DM * vmv.x * k0 + I0, a1 = DM * vmv.y * k1 + I1;
    float b0 = DS * vsv.x * k0 + I0, b1 = DS * vsv.y * k1 + I1;
    s0 = ((a0 - b0) > TH) ? 1.f : 0.f;
    s1 = ((a1 - b1) > TH) ? 1.f : 0.f;
    *(float2*)(vm + idx) = make_float2(a0, a1);
    *(float2*)(vs + idx) = make_float2(b0, b1);
}

// Small zeroing only: fc states, output accumulator, guarded spike buffers.
__global__ void zero_small() {
    int stride = gridDim.x * blockDim.x;
    int i0 = blockIdx.x * blockDim.x + threadIdx.x;
    for (int i = i0; i < N_L3; i += stride) { g_vm3[i] = 0.f; g_vs3[i] = 0.f; }
    for (int i = i0; i < N_L4; i += stride) { g_vm4[i] = 0.f; g_vs4[i] = 0.f; g_out[i] = 0.f; }
    unsigned* a = (unsigned*)g_s0b;
    for (int i = i0; i < SZ_S0B; i += stride) a[i] = 0u;   /* both buffers */
    unsigned* c = (unsigned*)g_p1b;
    for (int i = i0; i < SZ_P1B / 2; i += stride) c[i] = 0u;
}

__device__ __forceinline__ unsigned pick_split_pack_h(float wa, float wb, int split) {
    __half ha = __float2half_rn(wa);
    __half hb = __float2half_rn(wb);
    __half va, vb;
    if (split == 0) { va = ha; vb = hb; }
    else {
        va = __float2half_rn((wa - __half2float(ha)) * 4096.0f);
        vb = __float2half_rn((wb - __half2float(hb)) * 4096.0f);
    }
    return (unsigned)__half_as_ushort(va) | ((unsigned)__half_as_ushort(vb) << 16);
}

__global__ void pack_w(const float* __restrict__ W, uint4* __restrict__ Bpk, int CIN, int total) {
    int idx = blockIdx.x * 256 + threadIdx.x;
    if (idx >= total) return;
    int KC = CIN / 16;
    int lane = idx & 31;
    int p = (idx >> 5) & 7;
    int rest = idx >> 8;
    int kc = rest % KC; rest /= KC;
    int split = rest & 1; int tap = rest >> 1;
    int ky = tap / 3, kx = tap % 3;
    int k0 = kc * 16 + (lane & 3) * 2;
    int n0 = (2 * p) * 8 + (lane >> 2);
    int n1 = n0 + 8;
    uint4 v;
    {
        float w0 = W[((size_t)(n0 * CIN + k0 + 0) * 3 + ky) * 3 + kx];
        float w1 = W[((size_t)(n0 * CIN + k0 + 1) * 3 + ky) * 3 + kx];
        float w8 = W[((size_t)(n0 * CIN + k0 + 8) * 3 + ky) * 3 + kx];
        float w9 = W[((size_t)(n0 * CIN + k0 + 9) * 3 + ky) * 3 + kx];
        v.x = pick_split_pack_h(w0, w1, split);
        v.y = pick_split_pack_h(w8, w9, split);
    }
    {
        float w0 = W[((size_t)(n1 * CIN + k0 + 0) * 3 + ky) * 3 + kx];
        float w1 = W[((size_t)(n1 * CIN + k0 + 1) * 3 + ky) * 3 + kx];
        float w8 = W[((size_t)(n1 * CIN + k0 + 8) * 3 + ky) * 3 + kx];
        float w9 = W[((size_t)(n1 * CIN + k0 + 9) * 3 + ky) * 3 + kx];
        v.z = pick_split_pack_h(w0, w1, split);
        v.w = pick_split_pack_h(w8, w9, split);
    }
    Bpk[idx] = v;
}

__global__ void __launch_bounds__(256)
conv0_srm(const float* __restrict__ x, const float* __restrict__ W0, int t, int first,
          __half* __restrict__ s0out) {
    __shared__ float ins[2 * 360];
    __shared__ float ws[16 * 2 * 12];
    __shared__ float sacc[256 * 17];
    int tid = threadIdx.x;
    int b = blockIdx.z, cog = blockIdx.y;
    int tX = blockIdx.x & 3, tY = blockIdx.x >> 2;
    int x0 = tX * 16, y0 = tY * 16;
    const float* xb = x + ((size_t)(b * 16 + t)) * 2 * 4096;
    for (int i = tid; i < 2 * 324; i += 256) {
        int ci = i / 324; int r = i - ci * 324;
        int y = r / 18;   int xq = r - y * 18;
        int gy = y0 + y - 1, gx = x0 + xq - 1;
        float v = 0.f;
        if ((unsigned)gy < 64u && (unsigned)gx < 64u) {
            v = __ldg(xb + ci * 4096 + gy * 64 + gx);
            v = fminf(fmaxf(v, 0.f), 1.f);
        }
        ins[ci * 360 + y * 20 + xq] = v;
    }
    for (int i = tid; i < 16 * 18; i += 256) {
        int col = i / 18; int r = i - col * 18;
        int ci = r / 9;   int k = r - ci * 9;
        ws[(col * 2 + ci) * 12 + k] = __ldg(W0 + ((size_t)(cog * 16 + col) * 2 + ci) * 9 + k);
    }
    __syncthreads();
    int ty = tid >> 4, tx = tid & 15;
    float acc[16];
#pragma unroll
    for (int j = 0; j < 16; j++) acc[j] = 0.f;
#pragma unroll
    for (int ci = 0; ci < 2; ci++) {
        const float* ip = ins + ci * 360 + ty * 20 + tx;
        float iv[3][3];
#pragma unroll
        for (int yy = 0; yy < 3; yy++)
#pragma unroll
            for (int xx = 0; xx < 3; xx++) iv[yy][xx] = ip[yy * 20 + xx];
#pragma unroll
        for (int j = 0; j < 16; j++) {
            const float* wb = ws + (j * 2 + ci) * 12;
            float4 wA = *(const float4*)wb;
            float4 wB = *(const float4*)(wb + 4);
            float w8 = wb[8];
            float s = acc[j];
            s += iv[0][0] * wA.x; s += iv[0][1] * wA.y; s += iv[0][2] * wA.z;
            s += iv[1][0] * wA.w; s += iv[1][1] * wB.x; s += iv[1][2] * wB.y;
            s += iv[2][0] * wB.z; s += iv[2][1] * wB.w; s += iv[2][2] * w8;
            acc[j] = s;
        }
    }
#pragma unroll
    for (int c = 0; c < 16; c++) sacc[(ty * 16 + tx) * 17 + c] = acc[c];
    __syncthreads();
#pragma unroll
    for (int q = 0; q < 4; q++) {
        int f = q * 256 + tid;
        int yl = f >> 6, fi = f & 63;
        int xl = fi >> 2, cq = fi & 3;
        size_t rowb = (((size_t)(cog * 16 + b) * 4096) + (y0 + yl) * 64 + x0) * 16;
        float4 vmv, vsv;
        if (first) { vmv = make_float4(0.f, 0.f, 0.f, 0.f); vsv = vmv; }
        else {
            vmv = *(float4*)(g_vm0 + rowb + fi * 4);
            vsv = *(float4*)(g_vs0 + rowb + fi * 4);
        }
        const float* sp = sacc + (yl * 16 + xl) * 17 + cq * 4;
        float I0 = sp[0], I1 = sp[1], I2 = sp[2], I3 = sp[3];
        float k0 = ((vmv.x - vsv.x) > TH) ? 0.f : 1.f;
        float k1 = ((vmv.y - vsv.y) > TH) ? 0.f : 1.f;
        float k2 = ((vmv.z - vsv.z) > TH) ? 0.f : 1.f;
        float k3 = ((vmv.w - vsv.w) > TH) ? 0.f : 1.f;
        float a0 = DM * vmv.x * k0 + I0, a1 = DM * vmv.y * k1 + I1;
        float a2 = DM * vmv.z * k2 + I2, a3 = DM * vmv.w * k3 + I3;
        float c0 = DS * vsv.x * k0 + I0, c1 = DS * vsv.y * k1 + I1;
        float c2 = DS * vsv.z * k2 + I2, c3 = DS * vsv.w * k3 + I3;
        float s0 = ((a0 - c0) > TH) ? 1.f : 0.f;
        float s1 = ((a1 - c1) > TH) ? 1.f : 0.f;
        float s2 = ((a2 - c2) > TH) ? 1.f : 0.f;
        float s3 = ((a3 - c3) > TH) ? 1.f : 0.f;
        *(float4*)(g_vm0 + rowb + fi * 4) = make_float4(a0, a1, a2, a3);
        *(float4*)(g_vs0 + rowb + fi * 4) = make_float4(c0, c1, c2, c3);
        int gy = y0 + yl, gx = x0 + xl;
        size_t qi = ((size_t)b * 4356 + (gy + 1) * 66 + (gx + 1)) * 64 + cog * 16 + cq * 4;
        *(__half2*)(s0out + qi)     = __floats2half2_rn(s0, s1);
        *(__half2*)(s0out + qi + 2) = __floats2half2_rn(s2, s3);
    }
}

__device__ __forceinline__ void mma16816h(float* c, const unsigned* a, unsigned b0, unsigned b1) {
    asm volatile(
        "mma.sync.aligned.m16n8k16.row.col.f32.f16.f16.f32 "
        "{%0,%1,%2,%3}, {%4,%5,%6,%7}, {%8,%9}, {%0,%1,%2,%3};\n"
        : "+f"(c[0]), "+f"(c[1]), "+f"(c[2]), "+f"(c[3])
        : "r"(a[0]), "r"(a[1]), "r"(a[2]), "r"(a[3]), "r"(b0), "r"(b1));
}

__device__ __forceinline__ void ldsm4(unsigned& r0, unsigned& r1, unsigned& r2, unsigned& r3,
                                      uint32_t addr) {
    asm volatile("ldmatrix.sync.aligned.m8n8.x4.shared.b16 {%0,%1,%2,%3}, [%4];\n"
                 : "=r"(r0), "=r"(r1), "=r"(r2), "=r"(r3) : "r"(addr));
}

// Implicit-GEMM conv (round-13 proven config): JT=2, software-pipelined mainloop.
template<int HW, int CIN, int YROWS, int SHIFT, bool IS_CONV2>
__global__ void __launch_bounds__(256, 2)
conv_mma(const __half* __restrict__ Abuf, const uint4* __restrict__ Bpk,
         float* __restrict__ vm, float* __restrict__ vs, int first,
         __half* __restrict__ poolb, __half* __restrict__ p2out)
{
    const int WB = HW + 2, QTOT = WB * WB, KC = CIN / 16;
    const int PITCHE = CIN + 8;
    const int SLABROWS = (YROWS + 2) * WB;
    const int CPR = CIN / 8;
    const int JT = 2;
    extern __shared__ __align__(16) unsigned char dsm[];
    __half* As = (__half*)dsm;

    int tid = threadIdx.x, lane = tid & 31, wid = tid >> 5;
    int warp_m = wid >> 2, warp_n = wid & 3;
    int b = blockIdx.z;
    int cogBase = blockIdx.y * 32 * JT;
    int y0 = blockIdx.x * YROWS;
    int q0 = y0 * WB;

    for (int i = tid; i < SLABROWS * CPR; i += 256) {
        int rrow = i / CPR, cw = i - rrow * CPR;
        uint4 v = __ldg((const uint4*)(Abuf + ((size_t)b * QTOT + q0 + rrow) * CIN) + cw);
        *(uint4*)(As + rrow * PITCHE + cw * 8) = v;
    }
    __syncthreads();

    int mtg[4];
#pragma unroll
    for (int l = 0; l < 4; l++)
        mtg[l] = (YROWS == 2) ? (warp_m * 2 + (l & 1) + ((l & 2) << 1)) : (warp_m * 4 + l);

    uint32_t sm32 = (uint32_t)__cvta_generic_to_shared(As);
    uint32_t abase[4];
#pragma unroll
    for (int l = 0; l < 4; l++) {
        int m = mtg[l] * 16 + (lane & 15);
        int pr = (m >> SHIFT) * WB + (m & (HW - 1));
        abase[l] = sm32 + (uint32_t)(pr * PITCHE * 2) + ((lane >> 4) & 1) * 16;
    }

    float acc[2][4][JT][4];
#pragma unroll
    for (int s = 0; s < 2; s++)
#pragma unroll
        for (int l = 0; l < 4; l++)
#pragma unroll
            for (int j = 0; j < JT; j++)
#pragma unroll
                for (int c = 0; c < 4; c++) acc[s][l][j][c] = 0.f;

    int ntp = cogBase / 16 + warp_n;
    const uint4* btl = Bpk + (size_t)ntp * 32 + lane;

#pragma unroll 1
    for (int tap = 0; tap < 9; tap++) {
        int ky = tap / 3, kx = tap - ky * 3;
        uint32_t ta[4];
#pragma unroll
        for (int l = 0; l < 4; l++) ta[l] = abase[l] + (uint32_t)((ky * WB + kx) * PITCHE * 2);
        const uint4* bt = btl + (size_t)tap * (2 * KC * 256);

        unsigned a[2][4][4];
#pragma unroll
        for (int l = 0; l < 4; l++)
            ldsm4(a[0][l][0], a[0][l][1], a[0][l][2], a[0][l][3], ta[l]);
        uint4 bb = __ldg(bt);

#pragma unroll
        for (int kc = 0; kc < KC; kc++) {
            int cur = kc & 1, nxt = cur ^ 1;
            if (kc + 1 < KC) {
#pragma unroll
                for (int l = 0; l < 4; l++)
                    ldsm4(a[nxt][l][0], a[nxt][l][1], a[nxt][l][2], a[nxt][l][3],
                          ta[l] + (kc + 1) * 32);
            }
#pragma unroll
            for (int s = 0; s < 2; s++) {
                uint4 bbn = bb;
                if (s == 0)               bbn = __ldg(bt + (KC + kc) * 256);
                else if (kc + 1 < KC)     bbn = __ldg(bt + (kc + 1) * 256);
#pragma unroll
                for (int l = 0; l < 4; l++) {
                    mma16816h(acc[s][l][0], a[cur][l], bb.x, bb.y);
                    mma16816h(acc[s][l][1], a[cur][l], bb.z, bb.w);
                }
                bb = bbn;
            }
        }
    }

#pragma unroll
    for (int lp = 0; lp < 2; lp++) {
#pragma unroll
        for (int o = 0; o < 2; o++) {
            int mA = mtg[lp] * 16 + (lane >> 2) + o * 8;
            int mB = mtg[lp + 2] * 16 + (lane >> 2) + o * 8;
            int yA = y0 + (mA >> SHIFT), xA = mA & (HW - 1);
            int yB = y0 + (mB >> SHIFT);
#pragma unroll
            for (int j = 0; j < JT; j++) {
                int co = cogBase + warp_n * 8 * JT + j * 8 + (lane & 3) * 2;
                size_t iA = ((size_t)(b * HW * HW) + yA * HW + xA) * 128 + co;
                size_t iB = ((size_t)(b * HW * HW) + yB * HW + xA) * 128 + co;
                float IA0 = acc[0][lp][j][o * 2 + 0]     + acc[1][lp][j][o * 2 + 0]     * INVSC;
                float IA1 = acc[0][lp][j][o * 2 + 1]     + acc[1][lp][j][o * 2 + 1]     * INVSC;
                float IB0 = acc[0][lp + 2][j][o * 2 + 0] + acc[1][lp + 2][j][o * 2 + 0] * INVSC;
                float IB1 = acc[0][lp + 2][j][o * 2 + 1] + acc[1][lp + 2][j][o * 2 + 1] * INVSC;
                float sA0, sA1, sB0, sB1;
                srm2_nsf(IA0, IA1, vm, vs, iA, first, sA0, sA1);
                srm2_nsf(IB0, IB1, vm, vs, iB, first, sB0, sB1);
                float xA0 = fmaxf(sA0, __shfl_xor_sync(0xffffffffu, sA0, 4));
                float xA1 = fmaxf(sA1, __shfl_xor_sync(0xffffffffu, sA1, 4));
                float xB0 = fmaxf(sB0, __shfl_xor_sync(0xffffffffu, sB0, 4));
                float xB1 = fmaxf(sB1, __shfl_xor_sync(0xffffffffu, sB1, 4));
                float p0 = fmaxf(xA0, xB0);
                float p1 = fmaxf(xA1, xB1);
                if ((lane & 4) == 0) {
                    int yp = yA >> 1, xp = xA >> 1;
                    if (IS_CONV2) {
                        p2out[(size_t)b * 32768 + co * 256 + yp * 16 + xp] = __float2half(p0);
                        p2out[(size_t)b * 32768 + (co + 1) * 256 + yp * 16 + xp] = __float2half(p1);
                    } else {
                        size_t qi = ((size_t)b * 1156 + (yp + 1) * 34 + (xp + 1)) * 128 + co;
                        *reinterpret_cast<__half2*>(poolb + qi) = __floats2half2_rn(p0, p1);
                    }
                }
            }
        }
    }
}

__global__ void __launch_bounds__(256)
fc3_partial(const float* __restrict__ W3, const __half* __restrict__ p2) {
    extern __shared__ __half p2s[];
    int ks = blockIdx.x, jg = blockIdx.y;
    int k0 = ks * 2048;
    int tid = threadIdx.x;
    for (int i = tid; i < 4096; i += 256) {
        int b = i >> 8, c = i & 255;
        ((uint4*)p2s)[i] = __ldg((const uint4*)(p2 + (size_t)b * 32768 + k0) + c);
    }
    __syncthreads();
    int wj = tid >> 5, lane = tid & 31;
    const uint2* ps = (const uint2*)p2s;
#pragma unroll 1
    for (int jj = 0; jj < 4; jj++) {
        int j = jg * 32 + wj * 4 + jj;
        const float4* wr = (const float4*)(W3 + (size_t)j * 32768 + k0);
        float acc[16];
#pragma unroll
        for (int b = 0; b < 16; b++) acc[b] = 0.f;
#pragma unroll 1
        for (int kk = lane; kk < 512; kk += 32) {
            float4 w4 = __ldg(wr + kk);
#pragma unroll
            for (int b = 0; b < 16; b++) {
                uint2 pv = ps[b * 512 + kk];
                float2 lo = __half22float2(*(const __half2*)&pv.x);
                float2 hi = __half22float2(*(const __half2*)&pv.y);
                acc[b] += w4.x * lo.x; acc[b] += w4.y * lo.y;
                acc[b] += w4.z * hi.x; acc[b] += w4.w * hi.y;
            }
        }
#pragma unroll
        for (int b = 0; b < 16; b++) {
            float v = acc[b];
            v += __shfl_down_sync(0xffffffffu, v, 16);
            v += __shfl_down_sync(0xffffffffu, v, 8);
            v += __shfl_down_sync(0xffffffffu, v, 4);
            v += __shfl_down_sync(0xffffffffu, v, 2);
            v += __shfl_down_sync(0xffffffffu, v, 1);
            if (lane == 0) g_part[(ks * 16 + b) * 512 + j] = v;
        }
    }
}

__global__ void __launch_bounds__(1024) fc34_srm(const float* __restrict__ W4) {
    __shared__ float s3s[8192];
    int tid = threadIdx.x;
#pragma unroll
    for (int e = 0; e < 8; e++) {
        int i = e * 1024 + tid;
        float I = 0.f;
#pragma unroll
        for (int ks = 0; ks < 16; ks++) I += g_part[ks * 8192 + i];
        s3s[i] = srm_ns(I, g_vm3, g_vs3, i);
    }
    __syncthreads();
    if (tid < 176) {
        int b = tid / 11, j = tid % 11;
        const float4* wr = (const float4*)(W4 + j * 512);
        const float4* sr = (const float4*)(s3s + b * 512);
        float acc = 0.f;
#pragma unroll 4
        for (int k = 0; k < 128; k++) {
            float4 w = __ldg(wr + k), s = sr[k];
            acc += w.x * s.x; acc += w.y * s.y; acc += w.z * s.z; acc += w.w * s.w;
        }
        float sn = srm_ns(acc, g_vm4, g_vs4, tid);
        g_out[tid] += sn;
    }
}

__global__ void finalize_k(float* __restrict__ out) {
    int i = threadIdx.x;
    if (i < 176) out[i] = g_out[i] * 0.0625f;
}

// ---------------------------------------------------------------------------
// Pipeline resources (round-13 schedule): created once at static init.
struct PipeCtx {
    cudaStream_t sA, sC;
    cudaEvent_t evInit, evJoinA, evJoinC;
    cudaEvent_t evA[16], evB1[16], evB2[16], evC3[16];
    PipeCtx() {
        cudaStreamCreateWithFlags(&sA, cudaStreamNonBlocking);
        cudaStreamCreateWithFlags(&sC, cudaStreamNonBlocking);
        cudaEventCreateWithFlags(&evInit, cudaEventDisableTiming);
        cudaEventCreateWithFlags(&evJoinA, cudaEventDisableTiming);
        cudaEventCreateWithFlags(&evJoinC, cudaEventDisableTiming);
        for (int i = 0; i < 16; i++) {
            cudaEventCreateWithFlags(&evA[i], cudaEventDisableTiming);
            cudaEventCreateWithFlags(&evB1[i], cudaEventDisableTiming);
            cudaEventCreateWithFlags(&evB2[i], cudaEventDisableTiming);
            cudaEventCreateWithFlags(&evC3[i], cudaEventDisableTiming);
        }
    }
};
static PipeCtx g_pipe;

extern "C" void kernel_launch(void* const* d_in, const int* in_sizes, int n_in,
                              void* d_out, int out_size) {
    (void)in_sizes; (void)n_in; (void)out_size;
    const float* x  = (const float*)d_in[0];
    const float* W0 = (const float*)d_in[1];
    const float* W1 = (const float*)d_in[2];
    const float* W2 = (const float*)d_in[3];
    const float* W3 = (const float*)d_in[4];
    const float* W4 = (const float*)d_in[5];
    float* out = (float*)d_out;

    const int SMEM1 = 264 * 144;
    const int SMEM2 = 204 * 272;
    cudaFuncSetAttribute((const void*)conv_mma<64, 64, 2, 6, false>,
                         cudaFuncAttributeMaxDynamicSharedMemorySize, SMEM1);
    cudaFuncSetAttribute((const void*)conv_mma<32, 128, 4, 5, true>,
                         cudaFuncAttributeMaxDynamicSharedMemorySize, SMEM2);
    cudaFuncSetAttribute((const void*)fc3_partial,
                         cudaFuncAttributeMaxDynamicSharedMemorySize, 65536);

    __half *s0b, *p1b, *p2b;
    uint4 *w1pk, *w2pk;
    float *vm1, *vs1, *vm2, *vs2;
    cudaGetSymbolAddress((void**)&s0b, g_s0b);
    cudaGetSymbolAddress((void**)&p1b, g_p1b);
    cudaGetSymbolAddress((void**)&p2b, g_p2b);
    cudaGetSymbolAddress((void**)&w1pk, g_w1pk);
    cudaGetSymbolAddress((void**)&w2pk, g_w2pk);
    cudaGetSymbolAddress((void**)&vm1, g_vm1);
    cudaGetSymbolAddress((void**)&vs1, g_vs1);
    cudaGetSymbolAddress((void**)&vm2, g_vm2);
    cudaGetSymbolAddress((void**)&vs2, g_vs2);

    zero_small<<<512, 256>>>();
    pack_w<<<(NW1PK4 + 255) / 256, 256>>>(W1, w1pk, 64, NW1PK4);
    pack_w<<<(NW2PK4 + 255) / 256, 256>>>(W2, w2pk, 128, NW2PK4);
    cudaEventRecord(g_pipe.evInit, 0);
    cudaStreamWaitEvent(g_pipe.sA, g_pipe.evInit, 0);

    for (int t = 0; t < 16; t++) {
        int first = (t == 0) ? 1 : 0;
        __half* s0t = s0b + (size_t)(t & 1) * SZ_S0B;
        __half* p2t = p2b + (size_t)(t & 1) * N_P2;

        // Stream A: conv0(t). Waits conv1(t-2) (s0b buffer reuse).
        if (t >= 2) cudaStreamWaitEvent(g_pipe.sA, g_pipe.evB1[t - 2], 0);
        conv0_srm<<<dim3(16, 4, 16), 256, 0, g_pipe.sA>>>(x, W0, t, first, s0t);
        cudaEventRecord(g_pipe.evA[t], g_pipe.sA);

        // Default stream B: conv1(t) (waits conv0(t)), conv2(t).
        cudaStreamWaitEvent(0, g_pipe.evA[t], 0);
        conv_mma<64, 64, 2, 6, false><<<dim3(32, 2, 16), 256, SMEM1>>>(
            s0t, w1pk, vm1, vs1, first, p1b, nullptr);
        cudaEventRecord(g_pipe.evB1[t], 0);
        if (t >= 2) cudaStreamWaitEvent(0, g_pipe.evC3[t - 2], 0);   // p2b reuse
        conv_mma<32, 128, 4, 5, true><<<dim3(8, 2, 16), 256, SMEM2>>>(
            p1b, w2pk, vm2, vs2, first, nullptr, p2t);
        cudaEventRecord(g_pipe.evB2[t], 0);

        // Stream C: fc3(t) (waits conv2(t)), fc34(t).
        cudaStreamWaitEvent(g_pipe.sC, g_pipe.evB2[t], 0);
        fc3_partial<<<dim3(16, 16), 256, 65536, g_pipe.sC>>>(W3, p2t);
        cudaEventRecord(g_pipe.evC3[t], g_pipe.sC);
        fc34_srm<<<1, 1024, 0, g_pipe.sC>>>(W4);
    }

    cudaEventRecord(g_pipe.evJoinA, g_pipe.sA);
    cudaEventRecord(g_pipe.evJoinC, g_pipe.sC);
    cudaStreamWaitEvent(0, g_pipe.evJoinA, 0);
    cudaStreamWaitEvent(0, g_pipe.evJoinC, 0);
    finalize_k<<<1, 256>>>(out);
}